// round 8
// baseline (speedup 1.0000x reference)
#include <cuda_runtime.h>
#include <cstdint>

#define E_TOT   30000
#define NB      10
#define WNUM    9216
#define EB      128
#define NTHR    512
#define INV_S3  0.5773502691896258f
#define PW0     0.10206207261596575f
#define PW1     0.17677669529663687f
#define PW1S    (PW1 * INV_S3)

#define NCH 102

__device__ float g_B1[51 * 2048];   // N=64 chunks, fragment-ordered
__device__ float g_B2[34 * 1024];   // N=32 chunks
__device__ float g_B3[17 * 1024];   // N=32 chunks (shared across m)

// SMEM float offsets
#define OFF_H    0        // [17][128]
#define OFF_HP   2176     // [17][128]
#define OFF_X0   4352     // [64][129]
#define OFF_ZAD  12608    // [32][129]
#define OFF_XC   16736    // [96][129]
#define OFF_SH0  29120    // [128]
#define OFF_SH1  29248    // [3][128]
#define OFF_BB   29632    // 3 x 2048 B staging
#define SMEM_FL  35776
#define SMEM_BYTES (SMEM_FL * 4)

__device__ __forceinline__ float tf32r(float v) {
    uint32_t r; asm("cvt.rna.tf32.f32 %0, %1;" : "=r"(r) : "f"(v));
    return __uint_as_float(r);
}
__device__ __forceinline__ uint32_t tf32u(float v) {
    uint32_t r; asm("cvt.rna.tf32.f32 %0, %1;" : "=r"(r) : "f"(v));
    return r;
}
__device__ __forceinline__ uint32_t smem_u32(const void* p) {
    uint32_t a;
    asm("{ .reg .u64 t; cvta.to.shared.u64 t, %1; cvt.u32.u64 %0, t; }" : "=r"(a) : "l"(p));
    return a;
}
__device__ __forceinline__ void cpa16(uint32_t s, const void* g) {
    asm volatile("cp.async.cg.shared.global [%0], [%1], 16;" :: "r"(s), "l"(g));
}
#define CP_COMMIT() asm volatile("cp.async.commit_group;")
#define CP_WAIT1()  asm volatile("cp.async.wait_group 1;")

__device__ __forceinline__ void mma8(float (&d)[4], const uint32_t (&a)[4],
                                     uint32_t b0, uint32_t b1) {
    asm volatile(
        "mma.sync.aligned.m16n8k8.row.col.f32.tf32.tf32.f32 "
        "{%0,%1,%2,%3}, {%4,%5,%6,%7}, {%8,%9}, {%0,%1,%2,%3};"
        : "+f"(d[0]), "+f"(d[1]), "+f"(d[2]), "+f"(d[3])
        : "r"(a[0]), "r"(a[1]), "r"(a[2]), "r"(a[3]), "r"(b0), "r"(b1));
}

// ---------------------------------------------------------------------------
// Prep: gather w2/b2 into fragment-ordered, tf32-rounded chunks (unchanged).
// ---------------------------------------------------------------------------
__global__ void prep_kernel(const float* __restrict__ w2, const float* __restrict__ b2) {
    int i = blockIdx.x * 256 + threadIdx.x;
    if (i < 51 * 2048) {                       // B1 (NT=8, N=64)
        int c = i >> 11, w = i & 2047;
        int lane = (w >> 1) & 31, p = w & 1, q = w >> 6;
        int ks = q >> 3, nt = q & 7;
        int j = c / 17, k = c % 17;
        int kk = ks * 8 + (lane & 3) + p * 4;
        int n  = nt * 8 + (lane >> 2);
        int col = (j < 2) ? ((j * 32 + kk) * 64 + n) : (7168 + kk * 64 + n);
        float val = (k < 16) ? w2[k * WNUM + col] : b2[col];
        g_B1[c * 2048 + w] = tf32r(val);
        return;
    }
    i -= 51 * 2048;
    if (i < 34 * 1024) {                       // B2 (NT=4, N=32)
        int c = i >> 10, w = i & 1023;
        int lane = (w >> 1) & 31, p = w & 1, q = w >> 6;
        int ks = q >> 2, nt = q & 3;
        int j = c / 17, k = c % 17;
        int kk = ks * 8 + (lane & 3) + p * 4;
        int n  = nt * 8 + (lane >> 2);
        int col = 4096 + (j * 32 + kk) * 32 + n;
        float val = (k < 16) ? w2[k * WNUM + col] : b2[col];
        g_B2[c * 1024 + w] = tf32r(val);
        return;
    }
    i -= 34 * 1024;
    if (i < 17 * 1024) {                       // B3 (NT=4, N=32)
        int c = i >> 10, w = i & 1023;
        int lane = (w >> 1) & 31, p = w & 1, q = w >> 6;
        int ks = q >> 2, nt = q & 3;
        int k = c;
        int kk = ks * 8 + (lane & 3) + p * 4;
        int n  = nt * 8 + (lane >> 2);
        int col = 6144 + kk * 32 + n;
        float val = (k < 16) ? w2[k * WNUM + col] : b2[col];
        g_B3[c * 1024 + w] = tf32r(val);
    }
}

// ---------------------------------------------------------------------------
// Main kernel
// ---------------------------------------------------------------------------
__device__ __forceinline__ const float* chunk_src(int c, int& nfl) {
    if (c < 51) { nfl = 2048; return g_B1 + c * 2048; }
    if (c < 85) { nfl = 1024; return g_B2 + (c - 51) * 1024; }
    nfl = 1024; return g_B3 + (c - 85) * 1024;
}

__device__ __forceinline__ void stage_chunk(int c, uint32_t sbB, int t) {
    if (c < NCH) {
        int nfl; const float* src = chunk_src(c, nfl);
        uint32_t dst = sbB + (uint32_t)((c % 3) * 2048) * 4u;
        int units = nfl / 4;
        for (int u = t; u < units; u += NTHR)
            cpa16(dst + (uint32_t)u * 16u, src + u * 4);
    }
    CP_COMMIT();
}

// NT = total column-tiles; each warp handles NT/2 starting at nhalf*NT/2.
template<int NT>
__device__ __forceinline__ void run_seg(
    int cbase, const float* __restrict__ hb,
    const float* __restrict__ fb,
    float (&acc)[NT/2][4],
    int eb, int lane, int nhalf, int t,
    const float* __restrict__ smemf, uint32_t sbB)
{
    const int NTL = NT / 2;
    const int r0 = lane >> 2, c0 = lane & 3;
    float Ff[4][4];
    #pragma unroll
    for (int ks = 0; ks < 4; ks++) {
        int v0 = ks * 8 + c0;
        Ff[ks][0] = fb[v0 * 129 + eb + r0];
        Ff[ks][1] = fb[v0 * 129 + eb + r0 + 8];
        Ff[ks][2] = fb[(v0 + 4) * 129 + eb + r0];
        Ff[ks][3] = fb[(v0 + 4) * 129 + eb + r0 + 8];
    }
    for (int k = 0; k < 17; k++) {
        int c = cbase + k;
        CP_WAIT1();
        __syncthreads();
        stage_chunk(c + 2, sbB, t);
        const float* Bb = smemf + OFF_BB + (c % 3) * 2048;
        float h0 = hb[k * 128 + eb + r0];
        float h1 = hb[k * 128 + eb + r0 + 8];
        uint32_t a[4][4];
        #pragma unroll
        for (int ks = 0; ks < 4; ks++) {
            a[ks][0] = tf32u(h0 * Ff[ks][0]);
            a[ks][1] = tf32u(h1 * Ff[ks][1]);
            a[ks][2] = tf32u(h0 * Ff[ks][2]);
            a[ks][3] = tf32u(h1 * Ff[ks][3]);
        }
        #pragma unroll
        for (int ntl = 0; ntl < NTL; ntl++) {
            int nt = nhalf * NTL + ntl;
            #pragma unroll
            for (int ks = 0; ks < 4; ks++) {
                float2 bv = *(const float2*)&Bb[(((ks * NT + nt) * 32) + lane) * 2];
                mma8(acc[ntl], a[ks], __float_as_uint(bv.x), __float_as_uint(bv.y));
            }
        }
    }
}

__device__ __forceinline__ void run_seg3(
    int cbase, const float* __restrict__ hb,
    const float* __restrict__ xcb,
    float (&pc)[3][2][4],
    int eb, int lane, int nhalf, int t,
    const float* __restrict__ smemf, uint32_t sbB)
{
    const int r0 = lane >> 2, c0 = lane & 3;
    float Ff[3][4][4];
    #pragma unroll
    for (int m = 0; m < 3; m++) {
        const float* fb = xcb + m * 129;
        #pragma unroll
        for (int ks = 0; ks < 4; ks++) {
            int v0 = ks * 8 + c0;
            Ff[m][ks][0] = fb[v0 * 387 + eb + r0];
            Ff[m][ks][1] = fb[v0 * 387 + eb + r0 + 8];
            Ff[m][ks][2] = fb[(v0 + 4) * 387 + eb + r0];
            Ff[m][ks][3] = fb[(v0 + 4) * 387 + eb + r0 + 8];
        }
    }
    for (int k = 0; k < 17; k++) {
        int c = cbase + k;
        CP_WAIT1();
        __syncthreads();
        stage_chunk(c + 2, sbB, t);
        const float* Bb = smemf + OFF_BB + (c % 3) * 2048;
        float h0 = hb[k * 128 + eb + r0];
        float h1 = hb[k * 128 + eb + r0 + 8];
        #pragma unroll
        for (int ks = 0; ks < 4; ks++) {
            uint32_t a[3][4];
            #pragma unroll
            for (int m = 0; m < 3; m++) {
                a[m][0] = tf32u(h0 * Ff[m][ks][0]);
                a[m][1] = tf32u(h1 * Ff[m][ks][1]);
                a[m][2] = tf32u(h0 * Ff[m][ks][2]);
                a[m][3] = tf32u(h1 * Ff[m][ks][3]);
            }
            #pragma unroll
            for (int ntl = 0; ntl < 2; ntl++) {
                int nt = nhalf * 2 + ntl;
                float2 bv = *(const float2*)&Bb[(((ks * 4 + nt) * 32) + lane) * 2];
                uint32_t b0 = __float_as_uint(bv.x), b1 = __float_as_uint(bv.y);
                #pragma unroll
                for (int m = 0; m < 3; m++)
                    mma8(pc[m][ntl], a[m], b0, b1);
            }
        }
    }
}

extern __shared__ float smem[];

__global__ void __launch_bounds__(NTHR, 1) conv_mma_kernel(
    const float* __restrict__ x,    const float* __restrict__ rps,
    const float* __restrict__ dist, const float* __restrict__ freq,
    const float* __restrict__ w1,   const float* __restrict__ b1,
    float* __restrict__ out)
{
    const int t     = threadIdx.x;
    const int wid   = t >> 5;
    const int lane  = t & 31;
    const int nhalf = wid >> 3;          // 0 or 1 : which N-half this warp owns
    const int eb    = (wid & 7) * 16;    // 16-edge strip
    const int e0    = blockIdx.x * EB;
    const uint32_t sbB = smem_u32(smem) + OFF_BB * 4;

    // prologue: prefetch chunks 0 and 1 (overlap all setup)
    stage_chunk(0, sbB, t);
    stage_chunk(1, sbB, t);

    // --- setup: radial MLP + sh ---
    if (t < EB) {
        int e = e0 + t;
        if (e < E_TOT) {
            float d  = dist[e] * 0.25f;
            float id = 1.0f / d;
            float d2 = d * d;
            float d5 = d2 * d2 * d;
            float env = id - 28.0f * d5 + 48.0f * d5 * d - 21.0f * d5 * d2;
            env = (d < 1.0f) ? env : 0.0f;
            float basis[NB];
            #pragma unroll
            for (int i = 0; i < NB; i++) basis[i] = env * sinf(freq[i] * d);
            float s0 = rps[e * 4 + 0];
            smem[OFF_SH0 + t]           = s0;
            smem[OFF_SH1 + 0 * 128 + t] = rps[e * 4 + 1];
            smem[OFF_SH1 + 1 * 128 + t] = rps[e * 4 + 2];
            smem[OFF_SH1 + 2 * 128 + t] = rps[e * 4 + 3];
            #pragma unroll
            for (int k = 0; k < 16; k++) {
                float pre = b1[k];
                #pragma unroll
                for (int i = 0; i < NB; i++) pre = fmaf(basis[i], w1[i * 16 + k], pre);
                float sg = 1.0f / (1.0f + expf(-pre));
                float hv = pre * sg;
                smem[OFF_H  + k * 128 + t] = hv;
                smem[OFF_HP + k * 128 + t] = hv * s0;
            }
            smem[OFF_H  + 16 * 128 + t] = 1.0f;
            smem[OFF_HP + 16 * 128 + t] = s0;
        } else {
            #pragma unroll
            for (int k = 0; k < 17; k++) {
                smem[OFF_H  + k * 128 + t] = 0.0f;
                smem[OFF_HP + k * 128 + t] = 0.0f;
            }
            smem[OFF_SH0 + t] = 0.0f;
            smem[OFF_SH1 + 0 * 128 + t] = 0.0f;
            smem[OFF_SH1 + 1 * 128 + t] = 0.0f;
            smem[OFF_SH1 + 2 * 128 + t] = 0.0f;
        }
    }

    // --- x tiles (transposed, stride 129) ---
    for (int idx = t; idx < EB * 40; idx += NTHR) {
        int el = idx / 40, c4 = idx - el * 40;
        int e  = e0 + el;
        float4 v = make_float4(0.f, 0.f, 0.f, 0.f);
        if (e < E_TOT) v = *(const float4*)&x[(size_t)e * 160 + c4 * 4];
        if (c4 < 16) {
            int vb = c4 * 4;
            smem[OFF_X0 + (vb + 0) * 129 + el] = v.x;
            smem[OFF_X0 + (vb + 1) * 129 + el] = v.y;
            smem[OFF_X0 + (vb + 2) * 129 + el] = v.z;
            smem[OFF_X0 + (vb + 3) * 129 + el] = v.w;
        } else {
            int vb = c4 * 4 - 64;
            smem[OFF_XC + (vb + 0) * 129 + el] = v.x;
            smem[OFF_XC + (vb + 1) * 129 + el] = v.y;
            smem[OFF_XC + (vb + 2) * 129 + el] = v.z;
            smem[OFF_XC + (vb + 3) * 129 + el] = v.w;
        }
    }
    __syncthreads();

    for (int idx = t; idx < 32 * 128; idx += NTHR) {
        int u = idx >> 7, el = idx & 127;
        float a = smem[OFF_XC + (u * 3 + 0) * 129 + el] * smem[OFF_SH1 + 0 * 128 + el]
                + smem[OFF_XC + (u * 3 + 1) * 129 + el] * smem[OFF_SH1 + 1 * 128 + el]
                + smem[OFF_XC + (u * 3 + 2) * 129 + el] * smem[OFF_SH1 + 2 * 128 + el];
        smem[OFF_ZAD + u * 129 + el] = INV_S3 * a;
    }
    __syncthreads();

    // --- phase 1: out0 (N=64 -> 4 tiles per warp) ---
    float acc1[4][4];
    #pragma unroll
    for (int i = 0; i < 4; i++) { acc1[i][0]=acc1[i][1]=acc1[i][2]=acc1[i][3]=0.f; }
    run_seg<8>(0,  smem + OFF_HP, smem + OFF_X0,            acc1, eb, lane, nhalf, t, smem, sbB);
    run_seg<8>(17, smem + OFF_HP, smem + OFF_X0 + 32 * 129, acc1, eb, lane, nhalf, t, smem, sbB);
    run_seg<8>(34, smem + OFF_H,  smem + OFF_ZAD,           acc1, eb, lane, nhalf, t, smem, sbB);

    // epilogue for out0 now (frees acc1 before later segments)
    const int r0 = lane >> 2, cpair = 2 * (lane & 3);
    #pragma unroll
    for (int ntl = 0; ntl < 4; ntl++) {
        int col = (nhalf * 4 + ntl) * 8 + cpair;
        int eA = e0 + eb + r0;
        if (eA < E_TOT)
            *(float2*)&out[(size_t)eA * 160 + col] =
                make_float2(PW0 * acc1[ntl][0], PW0 * acc1[ntl][1]);
        int eB = eA + 8;
        if (eB < E_TOT)
            *(float2*)&out[(size_t)eB * 160 + col] =
                make_float2(PW0 * acc1[ntl][2], PW0 * acc1[ntl][3]);
    }

    // --- phase 2: pb (N=32 -> 2 tiles per warp) ---
    float acc2[2][4];
    #pragma unroll
    for (int i = 0; i < 2; i++) { acc2[i][0]=acc2[i][1]=acc2[i][2]=acc2[i][3]=0.f; }
    run_seg<4>(51, smem + OFF_H, smem + OFF_X0,            acc2, eb, lane, nhalf, t, smem, sbB);
    run_seg<4>(68, smem + OFF_H, smem + OFF_X0 + 32 * 129, acc2, eb, lane, nhalf, t, smem, sbB);

    // --- phase 3: pc (N=32 -> 2 tiles per warp, x3 m) ---
    float pc[3][2][4];
    #pragma unroll
    for (int m = 0; m < 3; m++)
        #pragma unroll
        for (int i = 0; i < 2; i++) { pc[m][i][0]=pc[m][i][1]=pc[m][i][2]=pc[m][i][3]=0.f; }
    run_seg3(85, smem + OFF_H, smem + OFF_XC, pc, eb, lane, nhalf, t, smem, sbB);

    // --- epilogue: out1 ---
    #pragma unroll
    for (int ntl = 0; ntl < 2; ntl++) {
        int w0 = (nhalf * 2 + ntl) * 8 + cpair;
        #pragma unroll
        for (int half = 0; half < 2; half++) {
            int el = eb + r0 + half * 8;
            int e  = e0 + el;
            if (e >= E_TOT) continue;
            float s0v = smem[OFF_SH0 + el];
            float s1v[3];
            #pragma unroll
            for (int m = 0; m < 3; m++) s1v[m] = smem[OFF_SH1 + m * 128 + el];
            float pb0 = acc2[ntl][half * 2 + 0];
            float pb1 = acc2[ntl][half * 2 + 1];
            float vals[6];
            #pragma unroll
            for (int m = 0; m < 3; m++) {
                vals[m]     = PW1S * (pb0 * s1v[m] + pc[m][ntl][half * 2 + 0] * s0v);
                vals[3 + m] = PW1S * (pb1 * s1v[m] + pc[m][ntl][half * 2 + 1] * s0v);
            }
            size_t base = (size_t)e * 160 + 64 + 3 * w0;
            *(float2*)&out[base + 0] = make_float2(vals[0], vals[1]);
            *(float2*)&out[base + 2] = make_float2(vals[2], vals[3]);
            *(float2*)&out[base + 4] = make_float2(vals[4], vals[5]);
        }
    }
}

extern "C" void kernel_launch(void* const* d_in, const int* in_sizes, int n_in,
                              void* d_out, int out_size) {
    (void)in_sizes; (void)n_in; (void)out_size;
    const float* x    = (const float*)d_in[0];
    const float* rps  = (const float*)d_in[1];
    const float* dist = (const float*)d_in[2];
    const float* freq = (const float*)d_in[3];
    const float* w1   = (const float*)d_in[4];
    const float* b1   = (const float*)d_in[5];
    const float* w2   = (const float*)d_in[6];
    const float* b2   = (const float*)d_in[7];
    float* out = (float*)d_out;

    const int tot = 51 * 2048 + 34 * 1024 + 17 * 1024;
    prep_kernel<<<(tot + 255) / 256, 256>>>(w2, b2);

    cudaFuncSetAttribute(conv_mma_kernel,
                         cudaFuncAttributeMaxDynamicSharedMemorySize, SMEM_BYTES);
    const int nblocks = (E_TOT + EB - 1) / EB;   // 235
    conv_mma_kernel<<<nblocks, NTHR, SMEM_BYTES>>>(x, rps, dist, freq, w1, b1, out);
}

// round 9
// speedup vs baseline: 1.3712x; 1.3712x over previous
#include <cuda_runtime.h>
#include <cstdint>

#define E_TOT   30000
#define NB      10
#define WNUM    9216
#define EB      128
#define NTHR    256
#define INV_S3  0.5773502691896258f
#define PW0     0.10206207261596575f
#define PW1     0.17677669529663687f
#define PW1S    (PW1 * INV_S3)

#define NCH 102

__device__ float g_B1[51 * 2048];   // N=64 chunks: j=0,1 -> Wa halves, j=2 -> Wd
__device__ float g_B2[34 * 1024];   // N=32 chunks: Wb halves
__device__ float g_B3[17 * 1024];   // N=32 chunks: Wc (shared across m)

// SMEM float offsets (total 27424 floats = 107.1 KB -> 2 CTAs/SM)
#define OFF_H    0        // [17][128]
#define OFF_X0   2176     // [64][129]  (later: zAd in rows 0-31, pb stash above)
#define OFF_ZAD  OFF_X0               // 32*129 = 4128 floats
#define OFF_PB   (OFF_X0 + 4128)      // pb stash [32][129] w-major
#define OFF_XC   10432    // [96][129]
#define OFF_SH0  22816    // [128]
#define OFF_SH1  22944    // [3][128]
#define OFF_BB   23328    // 2 x 2048 B staging
#define SMEM_FL  27424
#define SMEM_BYTES (SMEM_FL * 4)

__device__ __forceinline__ float tf32r(float v) {
    uint32_t r; asm("cvt.rna.tf32.f32 %0, %1;" : "=r"(r) : "f"(v));
    return __uint_as_float(r);
}
__device__ __forceinline__ uint32_t tf32u(float v) {
    uint32_t r; asm("cvt.rna.tf32.f32 %0, %1;" : "=r"(r) : "f"(v));
    return r;
}
__device__ __forceinline__ uint32_t smem_u32(const void* p) {
    uint32_t a;
    asm("{ .reg .u64 t; cvta.to.shared.u64 t, %1; cvt.u32.u64 %0, t; }" : "=r"(a) : "l"(p));
    return a;
}
__device__ __forceinline__ void cpa16(uint32_t s, const void* g) {
    asm volatile("cp.async.cg.shared.global [%0], [%1], 16;" :: "r"(s), "l"(g));
}
#define CP_COMMIT() asm volatile("cp.async.commit_group;")
#define CP_WAIT0()  asm volatile("cp.async.wait_group 0;")

__device__ __forceinline__ void mma8(float (&d)[4], const uint32_t (&a)[4],
                                     uint32_t b0, uint32_t b1) {
    asm volatile(
        "mma.sync.aligned.m16n8k8.row.col.f32.tf32.tf32.f32 "
        "{%0,%1,%2,%3}, {%4,%5,%6,%7}, {%8,%9}, {%0,%1,%2,%3};"
        : "+f"(d[0]), "+f"(d[1]), "+f"(d[2]), "+f"(d[3])
        : "r"(a[0]), "r"(a[1]), "r"(a[2]), "r"(a[3]), "r"(b0), "r"(b1));
}

// ---------------------------------------------------------------------------
// Prep: gather w2/b2 into fragment-ordered, tf32-rounded chunks (as R7).
// ---------------------------------------------------------------------------
__global__ void prep_kernel(const float* __restrict__ w2, const float* __restrict__ b2) {
    int i = blockIdx.x * 256 + threadIdx.x;
    if (i < 51 * 2048) {                       // B1 (NT=8, N=64)
        int c = i >> 11, w = i & 2047;
        int lane = (w >> 1) & 31, p = w & 1, q = w >> 6;
        int ks = q >> 3, nt = q & 7;
        int j = c / 17, k = c % 17;
        int kk = ks * 8 + (lane & 3) + p * 4;
        int n  = nt * 8 + (lane >> 2);
        int col = (j < 2) ? ((j * 32 + kk) * 64 + n) : (7168 + kk * 64 + n);
        float val = (k < 16) ? w2[k * WNUM + col] : b2[col];
        g_B1[c * 2048 + w] = tf32r(val);
        return;
    }
    i -= 51 * 2048;
    if (i < 34 * 1024) {                       // B2 (NT=4, N=32)
        int c = i >> 10, w = i & 1023;
        int lane = (w >> 1) & 31, p = w & 1, q = w >> 6;
        int ks = q >> 2, nt = q & 3;
        int j = c / 17, k = c % 17;
        int kk = ks * 8 + (lane & 3) + p * 4;
        int n  = nt * 8 + (lane >> 2);
        int col = 4096 + (j * 32 + kk) * 32 + n;
        float val = (k < 16) ? w2[k * WNUM + col] : b2[col];
        g_B2[c * 1024 + w] = tf32r(val);
        return;
    }
    i -= 34 * 1024;
    if (i < 17 * 1024) {                       // B3 (NT=4, N=32)
        int c = i >> 10, w = i & 1023;
        int lane = (w >> 1) & 31, p = w & 1, q = w >> 6;
        int ks = q >> 2, nt = q & 3;
        int k = c;
        int kk = ks * 8 + (lane & 3) + p * 4;
        int n  = nt * 8 + (lane >> 2);
        int col = 6144 + kk * 32 + n;
        float val = (k < 16) ? w2[k * WNUM + col] : b2[col];
        g_B3[c * 1024 + w] = tf32r(val);
    }
}

// ---------------------------------------------------------------------------
// Chunk consumption order (remapped for the new segment schedule):
//   [0,17)   Wa j=0 (B1 c 0-16)    N=64
//   [17,34)  Wa j=1 (B1 c 17-33)   N=64
//   [34,51)  Wb j=0 (B2 c 0-16)    N=32
//   [51,68)  Wb j=1 (B2 c 17-33)   N=32
//   [68,85)  Wd     (B1 c 34-50)   N=64
//   [85,102) Wc     (B3 c 0-16)    N=32
// ---------------------------------------------------------------------------
__device__ __forceinline__ const float* chunk_src(int c, int& nfl) {
    if (c < 34) { nfl = 2048; return g_B1 + c * 2048; }
    if (c < 68) { nfl = 1024; return g_B2 + (c - 34) * 1024; }
    if (c < 85) { nfl = 2048; return g_B1 + (c - 34) * 2048; }  // j=2 block at 34*2048
    nfl = 1024; return g_B3 + (c - 85) * 1024;
}

__device__ __forceinline__ void stage_chunk(int c, uint32_t sbB, int t) {
    if (c < NCH) {
        int nfl; const float* src = chunk_src(c, nfl);
        uint32_t dst = sbB + (uint32_t)((c & 1) * 2048) * 4u;
        int units = nfl / 4;
        for (int u = t; u < units; u += NTHR)
            cpa16(dst + (uint32_t)u * 16u, src + u * 4);
    }
    CP_COMMIT();
}

template<int NT>
__device__ __forceinline__ void run_seg(
    int cbase, const float* __restrict__ hb, float s00, float s01,
    const float* __restrict__ fb,
    float (&acc)[NT][4],
    int eb, int lane, int t,
    const float* __restrict__ smemf, uint32_t sbB)
{
    const int r0 = lane >> 2, c0 = lane & 3;
    float Ff[4][4];
    #pragma unroll
    for (int ks = 0; ks < 4; ks++) {
        int v0 = ks * 8 + c0;
        Ff[ks][0] = fb[v0 * 129 + eb + r0];
        Ff[ks][1] = fb[v0 * 129 + eb + r0 + 8];
        Ff[ks][2] = fb[(v0 + 4) * 129 + eb + r0];
        Ff[ks][3] = fb[(v0 + 4) * 129 + eb + r0 + 8];
    }
    for (int k = 0; k < 17; k++) {
        int c = cbase + k;
        CP_WAIT0();
        __syncthreads();
        stage_chunk(c + 1, sbB, t);
        const float* Bb = smemf + OFF_BB + (c & 1) * 2048;
        float h0 = hb[k * 128 + eb + r0] * s00;
        float h1 = hb[k * 128 + eb + r0 + 8] * s01;
        uint32_t a[4][4];
        #pragma unroll
        for (int ks = 0; ks < 4; ks++) {
            a[ks][0] = tf32u(h0 * Ff[ks][0]);
            a[ks][1] = tf32u(h1 * Ff[ks][1]);
            a[ks][2] = tf32u(h0 * Ff[ks][2]);
            a[ks][3] = tf32u(h1 * Ff[ks][3]);
        }
        #pragma unroll
        for (int nt = 0; nt < NT; nt++) {
            #pragma unroll
            for (int ks = 0; ks < 4; ks++) {
                float2 bv = *(const float2*)&Bb[(((ks * NT + nt) * 32) + lane) * 2];
                mma8(acc[nt], a[ks], __float_as_uint(bv.x), __float_as_uint(bv.y));
            }
        }
    }
}

__device__ __forceinline__ void run_seg3(
    int cbase, const float* __restrict__ hb,
    const float* __restrict__ xcb,
    float (&pc)[3][4][4],
    int eb, int lane, int t,
    const float* __restrict__ smemf, uint32_t sbB)
{
    const int r0 = lane >> 2, c0 = lane & 3;
    float Ff[3][4][4];
    #pragma unroll
    for (int m = 0; m < 3; m++) {
        const float* fb = xcb + m * 129;
        #pragma unroll
        for (int ks = 0; ks < 4; ks++) {
            int v0 = ks * 8 + c0;
            Ff[m][ks][0] = fb[v0 * 387 + eb + r0];
            Ff[m][ks][1] = fb[v0 * 387 + eb + r0 + 8];
            Ff[m][ks][2] = fb[(v0 + 4) * 387 + eb + r0];
            Ff[m][ks][3] = fb[(v0 + 4) * 387 + eb + r0 + 8];
        }
    }
    for (int k = 0; k < 17; k++) {
        int c = cbase + k;
        CP_WAIT0();
        __syncthreads();
        stage_chunk(c + 1, sbB, t);
        const float* Bb = smemf + OFF_BB + (c & 1) * 2048;
        float h0 = hb[k * 128 + eb + r0];
        float h1 = hb[k * 128 + eb + r0 + 8];
        #pragma unroll
        for (int m = 0; m < 3; m++) {
            uint32_t a[4][4];
            #pragma unroll
            for (int ks = 0; ks < 4; ks++) {
                a[ks][0] = tf32u(h0 * Ff[m][ks][0]);
                a[ks][1] = tf32u(h1 * Ff[m][ks][1]);
                a[ks][2] = tf32u(h0 * Ff[m][ks][2]);
                a[ks][3] = tf32u(h1 * Ff[m][ks][3]);
            }
            #pragma unroll
            for (int nt = 0; nt < 4; nt++) {
                #pragma unroll
                for (int ks = 0; ks < 4; ks++) {
                    float2 bv = *(const float2*)&Bb[(((ks * 4 + nt) * 32) + lane) * 2];
                    mma8(pc[m][nt], a[ks], __float_as_uint(bv.x), __float_as_uint(bv.y));
                }
            }
        }
    }
}

extern __shared__ float smem[];

__global__ void __launch_bounds__(NTHR, 2) conv_mma_kernel(
    const float* __restrict__ x,    const float* __restrict__ rps,
    const float* __restrict__ dist, const float* __restrict__ freq,
    const float* __restrict__ w1,   const float* __restrict__ b1,
    float* __restrict__ out)
{
    const int t    = threadIdx.x;
    const int wid  = t >> 5;
    const int lane = t & 31;
    const int eb   = wid * 16;
    const int e0   = blockIdx.x * EB;
    const uint32_t sbB = smem_u32(smem) + OFF_BB * 4;

    // prologue prefetch (overlaps setup)
    stage_chunk(0, sbB, t);

    // --- setup: radial MLP + sh ---
    if (t < EB) {
        int e = e0 + t;
        if (e < E_TOT) {
            float d  = dist[e] * 0.25f;
            float id = 1.0f / d;
            float d2 = d * d;
            float d5 = d2 * d2 * d;
            float env = id - 28.0f * d5 + 48.0f * d5 * d - 21.0f * d5 * d2;
            env = (d < 1.0f) ? env : 0.0f;
            float basis[NB];
            #pragma unroll
            for (int i = 0; i < NB; i++) basis[i] = env * sinf(freq[i] * d);
            float s0 = rps[e * 4 + 0];
            smem[OFF_SH0 + t]           = s0;
            smem[OFF_SH1 + 0 * 128 + t] = rps[e * 4 + 1];
            smem[OFF_SH1 + 1 * 128 + t] = rps[e * 4 + 2];
            smem[OFF_SH1 + 2 * 128 + t] = rps[e * 4 + 3];
            #pragma unroll
            for (int k = 0; k < 16; k++) {
                float pre = b1[k];
                #pragma unroll
                for (int i = 0; i < NB; i++) pre = fmaf(basis[i], w1[i * 16 + k], pre);
                float sg = 1.0f / (1.0f + expf(-pre));
                smem[OFF_H + k * 128 + t] = pre * sg;
            }
            smem[OFF_H + 16 * 128 + t] = 1.0f;
        } else {
            #pragma unroll
            for (int k = 0; k < 17; k++) smem[OFF_H + k * 128 + t] = 0.0f;
            smem[OFF_SH0 + t] = 0.0f;
            smem[OFF_SH1 + 0 * 128 + t] = 0.0f;
            smem[OFF_SH1 + 1 * 128 + t] = 0.0f;
            smem[OFF_SH1 + 2 * 128 + t] = 0.0f;
        }
    }

    // --- x tiles (transposed, stride 129) ---
    for (int idx = t; idx < EB * 40; idx += NTHR) {
        int el = idx / 40, c4 = idx - el * 40;
        int e  = e0 + el;
        float4 v = make_float4(0.f, 0.f, 0.f, 0.f);
        if (e < E_TOT) v = *(const float4*)&x[(size_t)e * 160 + c4 * 4];
        if (c4 < 16) {
            int vb = c4 * 4;
            smem[OFF_X0 + (vb + 0) * 129 + el] = v.x;
            smem[OFF_X0 + (vb + 1) * 129 + el] = v.y;
            smem[OFF_X0 + (vb + 2) * 129 + el] = v.z;
            smem[OFF_X0 + (vb + 3) * 129 + el] = v.w;
        } else {
            int vb = c4 * 4 - 64;
            smem[OFF_XC + (vb + 0) * 129 + el] = v.x;
            smem[OFF_XC + (vb + 1) * 129 + el] = v.y;
            smem[OFF_XC + (vb + 2) * 129 + el] = v.z;
            smem[OFF_XC + (vb + 3) * 129 + el] = v.w;
        }
    }
    __syncthreads();

    const float* H = smem + OFF_H;
    const float s00 = smem[OFF_SH0 + eb + (lane >> 2)];
    const float s01 = smem[OFF_SH0 + eb + (lane >> 2) + 8];

    // --- phase 1a/1b: Wa on x0 (A = h*sh0*x0), accumulate out0 ---
    float acc1[8][4];
    #pragma unroll
    for (int i = 0; i < 8; i++) { acc1[i][0]=acc1[i][1]=acc1[i][2]=acc1[i][3]=0.f; }
    run_seg<8>(0,  H, s00, s01, smem + OFF_X0,            acc1, eb, lane, t, smem, sbB);
    run_seg<8>(17, H, s00, s01, smem + OFF_X0 + 32 * 129, acc1, eb, lane, t, smem, sbB);

    // --- phase 2: Wb on x0 (A = h*x0) -> pb ---
    float acc2[4][4];
    #pragma unroll
    for (int i = 0; i < 4; i++) { acc2[i][0]=acc2[i][1]=acc2[i][2]=acc2[i][3]=0.f; }
    run_seg<4>(34, H, 1.0f, 1.0f, smem + OFF_X0,            acc2, eb, lane, t, smem, sbB);
    run_seg<4>(51, H, 1.0f, 1.0f, smem + OFF_X0 + 32 * 129, acc2, eb, lane, t, smem, sbB);

    // --- X0 region now dead: stash pb, build zAd ---
    __syncthreads();
    {
        const int r0 = lane >> 2, cpair = 2 * (lane & 3);
        float* pbS = smem + OFF_PB;
        #pragma unroll
        for (int nt = 0; nt < 4; nt++) {
            int w0 = nt * 8 + cpair;
            pbS[(w0 + 0) * 129 + eb + r0]     = acc2[nt][0];
            pbS[(w0 + 1) * 129 + eb + r0]     = acc2[nt][1];
            pbS[(w0 + 0) * 129 + eb + r0 + 8] = acc2[nt][2];
            pbS[(w0 + 1) * 129 + eb + r0 + 8] = acc2[nt][3];
        }
    }
    for (int idx = t; idx < 32 * 128; idx += NTHR) {
        int u = idx >> 7, el = idx & 127;
        float a = smem[OFF_XC + (u * 3 + 0) * 129 + el] * smem[OFF_SH1 + 0 * 128 + el]
                + smem[OFF_XC + (u * 3 + 1) * 129 + el] * smem[OFF_SH1 + 1 * 128 + el]
                + smem[OFF_XC + (u * 3 + 2) * 129 + el] * smem[OFF_SH1 + 2 * 128 + el];
        smem[OFF_ZAD + u * 129 + el] = INV_S3 * a;
    }
    __syncthreads();

    // --- phase 1c: Wd on zAd (A = h*zAd), completes out0 ---
    run_seg<8>(68, H, 1.0f, 1.0f, smem + OFF_ZAD, acc1, eb, lane, t, smem, sbB);

    // out0 epilogue (frees acc1)
    const int r0 = lane >> 2, cpair = 2 * (lane & 3);
    #pragma unroll
    for (int nt = 0; nt < 8; nt++) {
        int col = nt * 8 + cpair;
        int eA = e0 + eb + r0;
        if (eA < E_TOT)
            *(float2*)&out[(size_t)eA * 160 + col] =
                make_float2(PW0 * acc1[nt][0], PW0 * acc1[nt][1]);
        int eB = eA + 8;
        if (eB < E_TOT)
            *(float2*)&out[(size_t)eB * 160 + col] =
                make_float2(PW0 * acc1[nt][2], PW0 * acc1[nt][3]);
    }

    // --- phase 3: Wc on xc (per-m) -> pc ---
    float pcx[3][4][4];
    #pragma unroll
    for (int m = 0; m < 3; m++)
        #pragma unroll
        for (int i = 0; i < 4; i++) { pcx[m][i][0]=pcx[m][i][1]=pcx[m][i][2]=pcx[m][i][3]=0.f; }
    run_seg3(85, H, smem + OFF_XC, pcx, eb, lane, t, smem, sbB);

    // --- out1 epilogue ---
    const float* pbS = smem + OFF_PB;
    #pragma unroll
    for (int nt = 0; nt < 4; nt++) {
        int w0 = nt * 8 + cpair;
        #pragma unroll
        for (int half = 0; half < 2; half++) {
            int el = eb + r0 + half * 8;
            int e  = e0 + el;
            if (e >= E_TOT) continue;
            float s0v = smem[OFF_SH0 + el];
            float s1v[3];
            #pragma unroll
            for (int m = 0; m < 3; m++) s1v[m] = smem[OFF_SH1 + m * 128 + el];
            float pb0 = pbS[(w0 + 0) * 129 + el];
            float pb1 = pbS[(w0 + 1) * 129 + el];
            float vals[6];
            #pragma unroll
            for (int m = 0; m < 3; m++) {
                vals[m]     = PW1S * (pb0 * s1v[m] + pcx[m][nt][half * 2 + 0] * s0v);
                vals[3 + m] = PW1S * (pb1 * s1v[m] + pcx[m][nt][half * 2 + 1] * s0v);
            }
            size_t base = (size_t)e * 160 + 64 + 3 * w0;
            *(float2*)&out[base + 0] = make_float2(vals[0], vals[1]);
            *(float2*)&out[base + 2] = make_float2(vals[2], vals[3]);
            *(float2*)&out[base + 4] = make_float2(vals[4], vals[5]);
        }
    }
}

extern "C" void kernel_launch(void* const* d_in, const int* in_sizes, int n_in,
                              void* d_out, int out_size) {
    (void)in_sizes; (void)n_in; (void)out_size;
    const float* x    = (const float*)d_in[0];
    const float* rps  = (const float*)d_in[1];
    const float* dist = (const float*)d_in[2];
    const float* freq = (const float*)d_in[3];
    const float* w1   = (const float*)d_in[4];
    const float* b1   = (const float*)d_in[5];
    const float* w2   = (const float*)d_in[6];
    const float* b2   = (const float*)d_in[7];
    float* out = (float*)d_out;

    const int tot = 51 * 2048 + 34 * 1024 + 17 * 1024;
    prep_kernel<<<(tot + 255) / 256, 256>>>(w2, b2);

    cudaFuncSetAttribute(conv_mma_kernel,
                         cudaFuncAttributeMaxDynamicSharedMemorySize, SMEM_BYTES);
    const int nblocks = (E_TOT + EB - 1) / EB;   // 235
    conv_mma_kernel<<<nblocks, NTHR, SMEM_BYTES>>>(x, rps, dist, freq, w1, b1, out);
}

// round 10
// speedup vs baseline: 1.9726x; 1.4386x over previous
#include <cuda_runtime.h>
#include <cuda_fp16.h>
#include <cstdint>

#define E_TOT   30000
#define NB      10
#define WNUM    9216
#define EB      128
#define NTHR    256
#define INV_S3  0.5773502691896258f
#define PW0     0.10206207261596575f
#define PW1     0.17677669529663687f
#define PW1S    (PW1 * INV_S3)

#define NCH 102

// Packed half2 B fragments (u32 each), fragment-ordered per chunk.
__device__ uint32_t g_B1[51 * 1024];   // N=64 chunks: c<34 Wa halves, c>=34 Wd
__device__ uint32_t g_B2[34 * 512];    // N=32 chunks: Wb halves
__device__ uint32_t g_B3[17 * 512];    // N=32 chunks: Wc

// SMEM float offsets (26400 floats = 103.1 KB -> 2 CTAs/SM)
#define OFF_H    0        // [17][128]
#define OFF_X0   2176     // [64][129]  (later: zAd rows 0-31, pb stash above)
#define OFF_ZAD  OFF_X0
#define OFF_PB   (OFF_X0 + 4128)
#define OFF_XC   10432    // [96][129]
#define OFF_SH0  22816    // [128]
#define OFF_SH1  22944    // [3][128]
#define OFF_BB   23328    // 3 x 1024 u32 staging buffers
#define SMEM_FL  26400
#define SMEM_BYTES (SMEM_FL * 4)

__device__ __forceinline__ uint32_t pkh2(float lo, float hi) {
    __half2 h = __floats2half2_rn(lo, hi);
    return *reinterpret_cast<uint32_t*>(&h);
}
__device__ __forceinline__ uint32_t smem_u32(const void* p) {
    uint32_t a;
    asm("{ .reg .u64 t; cvta.to.shared.u64 t, %1; cvt.u32.u64 %0, t; }" : "=r"(a) : "l"(p));
    return a;
}
__device__ __forceinline__ void cpa16(uint32_t s, const void* g) {
    asm volatile("cp.async.cg.shared.global [%0], [%1], 16;" :: "r"(s), "l"(g));
}
#define CP_COMMIT() asm volatile("cp.async.commit_group;")
#define CP_WAIT1()  asm volatile("cp.async.wait_group 1;")
#define CP_WAIT0()  asm volatile("cp.async.wait_group 0;")

__device__ __forceinline__ void mma16(float (&d)[4], const uint32_t (&a)[4],
                                      uint32_t b0, uint32_t b1) {
    asm volatile(
        "mma.sync.aligned.m16n8k16.row.col.f32.f16.f16.f32 "
        "{%0,%1,%2,%3}, {%4,%5,%6,%7}, {%8,%9}, {%0,%1,%2,%3};"
        : "+f"(d[0]), "+f"(d[1]), "+f"(d[2]), "+f"(d[3])
        : "r"(a[0]), "r"(a[1]), "r"(a[2]), "r"(a[3]), "r"(b0), "r"(b1));
}

// ---------------------------------------------------------------------------
// Prep: gather w2/b2 into fp16 fragment-ordered chunks.
// u32 index within chunk = ((s*NT + nt)*32 + lane)*2 + p
//   kk (K within chunk) = s*16 + (lane&3)*2 + p*8  (+0/+1 -> lo/hi half)
//   n = nt*8 + (lane>>2)
// ---------------------------------------------------------------------------
__global__ void prep_kernel(const float* __restrict__ w2, const float* __restrict__ b2) {
    int i = blockIdx.x * 256 + threadIdx.x;
    if (i < 51 * 1024) {                       // B1 (NT=8, N=64)
        int c = i >> 10, w = i & 1023;
        int p = w & 1, lane = (w >> 1) & 31, q = w >> 6;   // q in [0,16)
        int s = q >> 3, nt = q & 7;
        int j = c / 17, k = c % 17;
        int kk = s * 16 + (lane & 3) * 2 + p * 8;
        int n  = nt * 8 + (lane >> 2);
        int col0 = (j < 2) ? ((j * 32 + kk) * 64 + n)     : (7168 + kk * 64 + n);
        int col1 = (j < 2) ? ((j * 32 + kk + 1) * 64 + n) : (7168 + (kk + 1) * 64 + n);
        float v0 = (k < 16) ? w2[k * WNUM + col0] : b2[col0];
        float v1 = (k < 16) ? w2[k * WNUM + col1] : b2[col1];
        g_B1[i] = pkh2(v0, v1);
        return;
    }
    i -= 51 * 1024;
    if (i < 34 * 512) {                        // B2 (NT=4, N=32)
        int c = i >> 9, w = i & 511;
        int p = w & 1, lane = (w >> 1) & 31, q = w >> 6;   // q in [0,8)
        int s = q >> 2, nt = q & 3;
        int j = c / 17, k = c % 17;
        int kk = s * 16 + (lane & 3) * 2 + p * 8;
        int n  = nt * 8 + (lane >> 2);
        int col0 = 4096 + (j * 32 + kk) * 32 + n;
        int col1 = 4096 + (j * 32 + kk + 1) * 32 + n;
        float v0 = (k < 16) ? w2[k * WNUM + col0] : b2[col0];
        float v1 = (k < 16) ? w2[k * WNUM + col1] : b2[col1];
        g_B2[c * 512 + w] = pkh2(v0, v1);
        return;
    }
    i -= 34 * 512;
    if (i < 17 * 512) {                        // B3 (NT=4, N=32)
        int c = i >> 9, w = i & 511;
        int p = w & 1, lane = (w >> 1) & 31, q = w >> 6;
        int s = q >> 2, nt = q & 3;
        int k = c;
        int kk = s * 16 + (lane & 3) * 2 + p * 8;
        int n  = nt * 8 + (lane >> 2);
        int col0 = 6144 + kk * 32 + n;
        int col1 = 6144 + (kk + 1) * 32 + n;
        float v0 = (k < 16) ? w2[k * WNUM + col0] : b2[col0];
        float v1 = (k < 16) ? w2[k * WNUM + col1] : b2[col1];
        g_B3[c * 512 + w] = pkh2(v0, v1);
    }
}

// Chunk consumption order (as R9):
//   [0,34) Wa (B1)  N=64 | [34,68) Wb (B2) N=32 | [68,85) Wd (B1) N=64 | [85,102) Wc (B3) N=32
__device__ __forceinline__ const uint32_t* chunk_src(int c, int& nu) {
    if (c < 34) { nu = 1024; return g_B1 + c * 1024; }
    if (c < 68) { nu = 512;  return g_B2 + (c - 34) * 512; }
    if (c < 85) { nu = 1024; return g_B1 + (c - 34) * 1024; }
    nu = 512; return g_B3 + (c - 85) * 512;
}

__device__ __forceinline__ void stage_chunk(int c, uint32_t sbB, int t) {
    if (c < NCH) {
        int nu; const uint32_t* src = chunk_src(c, nu);
        uint32_t dst = sbB + (uint32_t)((c % 3) * 1024) * 4u;
        int units = nu / 4;                 // 256 or 128 quads
        if (t < units) cpa16(dst + (uint32_t)t * 16u, src + t * 4);
    }
    CP_COMMIT();
}

template<int NT>
__device__ __forceinline__ void run_seg(
    int cbase, const float* __restrict__ hb, float s00, float s01,
    const float* __restrict__ fb,
    float (&acc)[NT][4],
    int eb, int lane, int t,
    const float* __restrict__ smemf, uint32_t sbB)
{
    const int r0 = lane >> 2;
    const int vb = (lane & 3) * 2;
    float Ff[2][4][2];
    #pragma unroll
    for (int s = 0; s < 2; s++) {
        int v0 = s * 16 + vb;
        Ff[s][0][0] = fb[(v0 + 0) * 129 + eb + r0];
        Ff[s][0][1] = fb[(v0 + 0) * 129 + eb + r0 + 8];
        Ff[s][1][0] = fb[(v0 + 1) * 129 + eb + r0];
        Ff[s][1][1] = fb[(v0 + 1) * 129 + eb + r0 + 8];
        Ff[s][2][0] = fb[(v0 + 8) * 129 + eb + r0];
        Ff[s][2][1] = fb[(v0 + 8) * 129 + eb + r0 + 8];
        Ff[s][3][0] = fb[(v0 + 9) * 129 + eb + r0];
        Ff[s][3][1] = fb[(v0 + 9) * 129 + eb + r0 + 8];
    }
    for (int k = 0; k < 17; k++) {
        int c = cbase + k;
        CP_WAIT1();
        __syncthreads();
        stage_chunk(c + 2, sbB, t);
        const uint2* Bb = (const uint2*)(smemf + OFF_BB + (c % 3) * 1024);
        float h0 = hb[k * 128 + eb + r0] * s00;
        float h1 = hb[k * 128 + eb + r0 + 8] * s01;
        #pragma unroll
        for (int s = 0; s < 2; s++) {
            uint32_t a[4];
            a[0] = pkh2(h0 * Ff[s][0][0], h0 * Ff[s][1][0]);
            a[1] = pkh2(h1 * Ff[s][0][1], h1 * Ff[s][1][1]);
            a[2] = pkh2(h0 * Ff[s][2][0], h0 * Ff[s][3][0]);
            a[3] = pkh2(h1 * Ff[s][2][1], h1 * Ff[s][3][1]);
            #pragma unroll
            for (int nt = 0; nt < NT; nt++) {
                uint2 bv = Bb[(s * NT + nt) * 32 + lane];
                mma16(acc[nt], a, bv.x, bv.y);
            }
        }
    }
}

__device__ __forceinline__ void run_seg3(
    int cbase, const float* __restrict__ hb,
    const float* __restrict__ xcb,
    float (&pc)[3][4][4],
    int eb, int lane, int t,
    const float* __restrict__ smemf, uint32_t sbB)
{
    const int r0 = lane >> 2;
    const int vb = (lane & 3) * 2;
    float Ff[3][2][4][2];
    #pragma unroll
    for (int m = 0; m < 3; m++) {
        const float* fb = xcb + m * 129;
        #pragma unroll
        for (int s = 0; s < 2; s++) {
            int v0 = s * 16 + vb;
            Ff[m][s][0][0] = fb[(v0 + 0) * 387 + eb + r0];
            Ff[m][s][0][1] = fb[(v0 + 0) * 387 + eb + r0 + 8];
            Ff[m][s][1][0] = fb[(v0 + 1) * 387 + eb + r0];
            Ff[m][s][1][1] = fb[(v0 + 1) * 387 + eb + r0 + 8];
            Ff[m][s][2][0] = fb[(v0 + 8) * 387 + eb + r0];
            Ff[m][s][2][1] = fb[(v0 + 8) * 387 + eb + r0 + 8];
            Ff[m][s][3][0] = fb[(v0 + 9) * 387 + eb + r0];
            Ff[m][s][3][1] = fb[(v0 + 9) * 387 + eb + r0 + 8];
        }
    }
    for (int k = 0; k < 17; k++) {
        int c = cbase + k;
        CP_WAIT1();
        __syncthreads();
        stage_chunk(c + 2, sbB, t);
        const uint2* Bb = (const uint2*)(smemf + OFF_BB + (c % 3) * 1024);
        float h0 = hb[k * 128 + eb + r0];
        float h1 = hb[k * 128 + eb + r0 + 8];
        #pragma unroll
        for (int s = 0; s < 2; s++) {
            uint32_t a[3][4];
            #pragma unroll
            for (int m = 0; m < 3; m++) {
                a[m][0] = pkh2(h0 * Ff[m][s][0][0], h0 * Ff[m][s][1][0]);
                a[m][1] = pkh2(h1 * Ff[m][s][0][1], h1 * Ff[m][s][1][1]);
                a[m][2] = pkh2(h0 * Ff[m][s][2][0], h0 * Ff[m][s][3][0]);
                a[m][3] = pkh2(h1 * Ff[m][s][2][1], h1 * Ff[m][s][3][1]);
            }
            #pragma unroll
            for (int nt = 0; nt < 4; nt++) {
                uint2 bv = Bb[(s * 4 + nt) * 32 + lane];
                #pragma unroll
                for (int m = 0; m < 3; m++)
                    mma16(pc[m][nt], a[m], bv.x, bv.y);
            }
        }
    }
}

extern __shared__ float smem[];

__global__ void __launch_bounds__(NTHR, 2) conv_mma_kernel(
    const float* __restrict__ x,    const float* __restrict__ rps,
    const float* __restrict__ dist, const float* __restrict__ freq,
    const float* __restrict__ w1,   const float* __restrict__ b1,
    float* __restrict__ out)
{
    const int t    = threadIdx.x;
    const int wid  = t >> 5;
    const int lane = t & 31;
    const int eb   = wid * 16;
    const int e0   = blockIdx.x * EB;
    const uint32_t sbB = smem_u32(smem) + OFF_BB * 4;

    // prologue: prefetch chunks 0,1 (overlaps setup)
    stage_chunk(0, sbB, t);
    stage_chunk(1, sbB, t);

    // --- setup: radial MLP + sh ---
    if (t < EB) {
        int e = e0 + t;
        if (e < E_TOT) {
            float d  = dist[e] * 0.25f;
            float id = 1.0f / d;
            float d2 = d * d;
            float d5 = d2 * d2 * d;
            float env = id - 28.0f * d5 + 48.0f * d5 * d - 21.0f * d5 * d2;
            env = (d < 1.0f) ? env : 0.0f;
            float basis[NB];
            #pragma unroll
            for (int i = 0; i < NB; i++) basis[i] = env * sinf(freq[i] * d);
            float s0 = rps[e * 4 + 0];
            smem[OFF_SH0 + t]           = s0;
            smem[OFF_SH1 + 0 * 128 + t] = rps[e * 4 + 1];
            smem[OFF_SH1 + 1 * 128 + t] = rps[e * 4 + 2];
            smem[OFF_SH1 + 2 * 128 + t] = rps[e * 4 + 3];
            #pragma unroll
            for (int k = 0; k < 16; k++) {
                float pre = b1[k];
                #pragma unroll
                for (int i = 0; i < NB; i++) pre = fmaf(basis[i], w1[i * 16 + k], pre);
                float sg = 1.0f / (1.0f + expf(-pre));
                smem[OFF_H + k * 128 + t] = pre * sg;
            }
            smem[OFF_H + 16 * 128 + t] = 1.0f;
        } else {
            #pragma unroll
            for (int k = 0; k < 17; k++) smem[OFF_H + k * 128 + t] = 0.0f;
            smem[OFF_SH0 + t] = 0.0f;
            smem[OFF_SH1 + 0 * 128 + t] = 0.0f;
            smem[OFF_SH1 + 1 * 128 + t] = 0.0f;
            smem[OFF_SH1 + 2 * 128 + t] = 0.0f;
        }
    }

    // --- x tiles (transposed, stride 129) ---
    for (int idx = t; idx < EB * 40; idx += NTHR) {
        int el = idx / 40, c4 = idx - el * 40;
        int e  = e0 + el;
        float4 v = make_float4(0.f, 0.f, 0.f, 0.f);
        if (e < E_TOT) v = *(const float4*)&x[(size_t)e * 160 + c4 * 4];
        if (c4 < 16) {
            int vb = c4 * 4;
            smem[OFF_X0 + (vb + 0) * 129 + el] = v.x;
            smem[OFF_X0 + (vb + 1) * 129 + el] = v.y;
            smem[OFF_X0 + (vb + 2) * 129 + el] = v.z;
            smem[OFF_X0 + (vb + 3) * 129 + el] = v.w;
        } else {
            int vb = c4 * 4 - 64;
            smem[OFF_XC + (vb + 0) * 129 + el] = v.x;
            smem[OFF_XC + (vb + 1) * 129 + el] = v.y;
            smem[OFF_XC + (vb + 2) * 129 + el] = v.z;
            smem[OFF_XC + (vb + 3) * 129 + el] = v.w;
        }
    }
    __syncthreads();

    const float* H = smem + OFF_H;
    const float s00 = smem[OFF_SH0 + eb + (lane >> 2)];
    const float s01 = smem[OFF_SH0 + eb + (lane >> 2) + 8];

    // --- phase 1a/1b: Wa on x0 (A = h*sh0*x0) ---
    float acc1[8][4];
    #pragma unroll
    for (int i = 0; i < 8; i++) { acc1[i][0]=acc1[i][1]=acc1[i][2]=acc1[i][3]=0.f; }
    run_seg<8>(0,  H, s00, s01, smem + OFF_X0,            acc1, eb, lane, t, smem, sbB);
    run_seg<8>(17, H, s00, s01, smem + OFF_X0 + 32 * 129, acc1, eb, lane, t, smem, sbB);

    // --- phase 2: Wb on x0 (A = h*x0) -> pb ---
    float acc2[4][4];
    #pragma unroll
    for (int i = 0; i < 4; i++) { acc2[i][0]=acc2[i][1]=acc2[i][2]=acc2[i][3]=0.f; }
    run_seg<4>(34, H, 1.0f, 1.0f, smem + OFF_X0,            acc2, eb, lane, t, smem, sbB);
    run_seg<4>(51, H, 1.0f, 1.0f, smem + OFF_X0 + 32 * 129, acc2, eb, lane, t, smem, sbB);

    // --- X0 dead: stash pb, build zAd ---
    __syncthreads();
    {
        const int r0 = lane >> 2, cpair = 2 * (lane & 3);
        float* pbS = smem + OFF_PB;
        #pragma unroll
        for (int nt = 0; nt < 4; nt++) {
            int w0 = nt * 8 + cpair;
            pbS[(w0 + 0) * 129 + eb + r0]     = acc2[nt][0];
            pbS[(w0 + 1) * 129 + eb + r0]     = acc2[nt][1];
            pbS[(w0 + 0) * 129 + eb + r0 + 8] = acc2[nt][2];
            pbS[(w0 + 1) * 129 + eb + r0 + 8] = acc2[nt][3];
        }
    }
    for (int idx = t; idx < 32 * 128; idx += NTHR) {
        int u = idx >> 7, el = idx & 127;
        float a = smem[OFF_XC + (u * 3 + 0) * 129 + el] * smem[OFF_SH1 + 0 * 128 + el]
                + smem[OFF_XC + (u * 3 + 1) * 129 + el] * smem[OFF_SH1 + 1 * 128 + el]
                + smem[OFF_XC + (u * 3 + 2) * 129 + el] * smem[OFF_SH1 + 2 * 128 + el];
        smem[OFF_ZAD + u * 129 + el] = INV_S3 * a;
    }
    __syncthreads();

    // --- phase 1c: Wd on zAd ---
    run_seg<8>(68, H, 1.0f, 1.0f, smem + OFF_ZAD, acc1, eb, lane, t, smem, sbB);

    // out0 epilogue
    const int r0 = lane >> 2, cpair = 2 * (lane & 3);
    #pragma unroll
    for (int nt = 0; nt < 8; nt++) {
        int col = nt * 8 + cpair;
        int eA = e0 + eb + r0;
        if (eA < E_TOT)
            *(float2*)&out[(size_t)eA * 160 + col] =
                make_float2(PW0 * acc1[nt][0], PW0 * acc1[nt][1]);
        int eB = eA + 8;
        if (eB < E_TOT)
            *(float2*)&out[(size_t)eB * 160 + col] =
                make_float2(PW0 * acc1[nt][2], PW0 * acc1[nt][3]);
    }

    // --- phase 3: Wc on xc -> pc ---
    float pcx[3][4][4];
    #pragma unroll
    for (int m = 0; m < 3; m++)
        #pragma unroll
        for (int i = 0; i < 4; i++) { pcx[m][i][0]=pcx[m][i][1]=pcx[m][i][2]=pcx[m][i][3]=0.f; }
    run_seg3(85, H, smem + OFF_XC, pcx, eb, lane, t, smem, sbB);

    // --- out1 epilogue ---
    const float* pbS = smem + OFF_PB;
    #pragma unroll
    for (int nt = 0; nt < 4; nt++) {
        int w0 = nt * 8 + cpair;
        #pragma unroll
        for (int half = 0; half < 2; half++) {
            int el = eb + r0 + half * 8;
            int e  = e0 + el;
            if (e >= E_TOT) continue;
            float s0v = smem[OFF_SH0 + el];
            float s1v[3];
            #pragma unroll
            for (int m = 0; m < 3; m++) s1v[m] = smem[OFF_SH1 + m * 128 + el];
            float pb0 = pbS[(w0 + 0) * 129 + el];
            float pb1 = pbS[(w0 + 1) * 129 + el];
            float vals[6];
            #pragma unroll
            for (int m = 0; m < 3; m++) {
                vals[m]     = PW1S * (pb0 * s1v[m] + pcx[m][nt][half * 2 + 0] * s0v);
                vals[3 + m] = PW1S * (pb1 * s1v[m] + pcx[m][nt][half * 2 + 1] * s0v);
            }
            size_t base = (size_t)e * 160 + 64 + 3 * w0;
            *(float2*)&out[base + 0] = make_float2(vals[0], vals[1]);
            *(float2*)&out[base + 2] = make_float2(vals[2], vals[3]);
            *(float2*)&out[base + 4] = make_float2(vals[4], vals[5]);
        }
    }
}

extern "C" void kernel_launch(void* const* d_in, const int* in_sizes, int n_in,
                              void* d_out, int out_size) {
    (void)in_sizes; (void)n_in; (void)out_size;
    const float* x    = (const float*)d_in[0];
    const float* rps  = (const float*)d_in[1];
    const float* dist = (const float*)d_in[2];
    const float* freq = (const float*)d_in[3];
    const float* w1   = (const float*)d_in[4];
    const float* b1   = (const float*)d_in[5];
    const float* w2   = (const float*)d_in[6];
    const float* b2   = (const float*)d_in[7];
    float* out = (float*)d_out;

    const int tot = 51 * 1024 + 34 * 512 + 17 * 512;
    prep_kernel<<<(tot + 255) / 256, 256>>>(w2, b2);

    cudaFuncSetAttribute(conv_mma_kernel,
                         cudaFuncAttributeMaxDynamicSharedMemorySize, SMEM_BYTES);
    const int nblocks = (E_TOT + EB - 1) / EB;   // 235
    conv_mma_kernel<<<nblocks, NTHR, SMEM_BYTES>>>(x, rps, dist, freq, w1, b1, out);
}